// round 4
// baseline (speedup 1.0000x reference)
#include <cuda_runtime.h>
#include <cuda_bf16.h>
#include <cstdint>

// CliffordISTA — Round 4: mma.sync bf16 hi/lo split GEMM, 2 CTA/SM, KT=32.
// out[c][b] = sum_k KT[c][k] * x[b][k];  v = hi + lo (bf16 split),
// D += Ahi*Bhi + Ahi*Blo + Alo*Bhi  (lo*lo dropped ~2^-16), fp32 accum.

#define BDIM 64
#define NB 8
#define MDIM 256
#define NDIM 512
#define NI 4096          // fwd inner dim / bwd out cols
#define MI 2048          // fwd out cols / bwd inner dim
#define NITER 50
#define STEPF 0.01f
#define KT 32            // K elems (bf16) per stage = 64B rows
#define MT 128           // M tile per CTA
#define FWD_SPLIT 16
#define BWD_SPLIT 8

#define BUF_BYTES 24576  // per stage: A_hi 8K | A_lo 8K | B_hi 4K | B_lo 4K
#define SMEM_TOTAL (2 * BUF_BYTES)

// ---------------- device globals ----------------
__device__ __nv_bfloat16 g_Kf_hi[(size_t)MI * NI];   // KfT[c][k], c=m*8+kb, k=n*8+i
__device__ __nv_bfloat16 g_Kf_lo[(size_t)MI * NI];
__device__ __nv_bfloat16 g_Kb_hi[(size_t)NI * MI];   // KbT[c][k], c=n*8+kb, k=m*8+i
__device__ __nv_bfloat16 g_Kb_lo[(size_t)NI * MI];
__device__ __nv_bfloat16 g_x_hi[BDIM * NI];          // x[b][k]
__device__ __nv_bfloat16 g_x_lo[BDIM * NI];
__device__ __nv_bfloat16 g_e_hi[BDIM * MI];          // err[b][k]
__device__ __nv_bfloat16 g_e_lo[BDIM * MI];
__device__ float g_xA[NI * BDIM];                    // fp32 x state, [c][b]
__device__ float g_xB[NI * BDIM];
__device__ float g_yT[MI * BDIM];                    // y transposed [c][b]
__device__ float g_pf[(size_t)FWD_SPLIT * MI * BDIM];  // [s][c*64+b]
__device__ float g_pb[(size_t)BWD_SPLIT * NI * BDIM];

// ---------------- helpers ----------------
__device__ __forceinline__ uint32_t smem_u32(const void* p) {
    uint32_t a;
    asm("{ .reg .u64 t; cvta.to.shared.u64 t, %1; cvt.u32.u64 %0, t; }" : "=r"(a) : "l"(p));
    return a;
}

#define CP_ASYNC16(smem, gptr) \
    asm volatile("cp.async.cg.shared.global [%0], [%1], 16;" :: "r"(smem), "l"(gptr))
#define CP_COMMIT() asm volatile("cp.async.commit_group;" ::: "memory")
#define CP_WAIT1()  asm volatile("cp.async.wait_group 1;" ::: "memory")
#define CP_WAIT0()  asm volatile("cp.async.wait_group 0;" ::: "memory")

__device__ __forceinline__ void ldsm4(uint32_t* r, uint32_t addr) {
    asm volatile("ldmatrix.sync.aligned.m8n8.x4.shared.b16 {%0,%1,%2,%3}, [%4];"
                 : "=r"(r[0]), "=r"(r[1]), "=r"(r[2]), "=r"(r[3]) : "r"(addr));
}

__device__ __forceinline__ void mma_bf16(float* c, const uint32_t* a, uint32_t b0, uint32_t b1) {
    asm volatile(
        "mma.sync.aligned.m16n8k16.row.col.f32.bf16.bf16.f32 "
        "{%0,%1,%2,%3}, {%4,%5,%6,%7}, {%8,%9}, {%0,%1,%2,%3};"
        : "+f"(c[0]), "+f"(c[1]), "+f"(c[2]), "+f"(c[3])
        : "r"(a[0]), "r"(a[1]), "r"(a[2]), "r"(a[3]), "r"(b0), "r"(b1));
}

__device__ __forceinline__ float csign(int i, int j) {
    int cnt = __popc((i >> 1) & j) + __popc((i >> 2) & j);
    return (cnt & 1) ? -1.0f : 1.0f;
}

__device__ __forceinline__ void split_bf16(float v, __nv_bfloat16* hi, __nv_bfloat16* lo) {
    __nv_bfloat16 h = __float2bfloat16(v);
    *hi = h;
    *lo = __float2bfloat16(v - __bfloat162float(h));
}

// ---------------- build / elementwise ----------------
__global__ void build_kf(const float* __restrict__ A) {
    size_t idx = (size_t)blockIdx.x * blockDim.x + threadIdx.x;
    if (idx >= (size_t)MI * NI) return;
    int c = (int)(idx >> 12), k = (int)(idx & (NI - 1));
    int m = c >> 3, kb = c & 7, n = k >> 3, i = k & 7, j = i ^ kb;
    float v = csign(i, j) * A[(m * NDIM + n) * NB + j];
    split_bf16(v, &g_Kf_hi[idx], &g_Kf_lo[idx]);
}

__global__ void build_kb(const float* __restrict__ A) {
    size_t idx = (size_t)blockIdx.x * blockDim.x + threadIdx.x;
    if (idx >= (size_t)NI * MI) return;
    int c = (int)(idx >> 11), k = (int)(idx & (MI - 1));
    int n = c >> 3, kb = c & 7, m = k >> 3, i = k & 7, j = i ^ kb;
    float rv = (__popc(j) >= 2) ? -1.0f : 1.0f;
    float v = csign(i, j) * rv * A[(m * NDIM + n) * NB + j];
    split_bf16(v, &g_Kb_hi[idx], &g_Kb_lo[idx]);
}

__global__ void build_yT(const float* __restrict__ y) {
    int idx = blockIdx.x * blockDim.x + threadIdx.x;
    if (idx >= MI * BDIM) return;
    int c = idx >> 6, b = idx & 63;
    g_yT[idx] = y[b * MI + c];
}

__global__ void init_x() {
    int idx = blockIdx.x * blockDim.x + threadIdx.x;
    if (idx >= BDIM * NI) return;
    g_xA[idx] = 0.0f;
    g_x_hi[idx] = __float2bfloat16(0.0f);
    g_x_lo[idx] = __float2bfloat16(0.0f);
}

// err_conv: block handles 32 c-rows x 64 b. Coalesced partial reads, smem
// transpose, coalesced bf16 writes to e[b][c].
__global__ __launch_bounds__(256) void err_conv() {
    __shared__ float tile[32][65];
    const int c0 = blockIdx.x * 32;
    const int t = threadIdx.x;
    {
        const int b = t & 63, cl0 = t >> 6;
#pragma unroll
        for (int i = 0; i < 8; i++) {
            int cl = cl0 + i * 4;
            int c = c0 + cl;
            float s = 0.0f;
#pragma unroll
            for (int p = 0; p < FWD_SPLIT; p++)
                s += g_pf[(size_t)p * MI * 64 + c * 64 + b];
            tile[cl][b] = s - g_yT[c * 64 + b];
        }
    }
    __syncthreads();
    {
        const int cl = t & 31, b0 = (t >> 5) * 8;
#pragma unroll
        for (int i = 0; i < 8; i++) {
            int b = b0 + i;
            float e = tile[cl][b];
            split_bf16(e, &g_e_hi[b * MI + c0 + cl], &g_e_lo[b * MI + c0 + cl]);
        }
    }
}

__global__ __launch_bounds__(256) void upd_x(const float* __restrict__ xin,
                                             float* __restrict__ xout) {
    __shared__ float tile[32][65];
    const int c0 = blockIdx.x * 32;
    const int t = threadIdx.x;
    {
        const int b = t & 63, cl0 = t >> 6;
#pragma unroll
        for (int i = 0; i < 8; i++) {
            int cl = cl0 + i * 4;
            int c = c0 + cl;
            float g = 0.0f;
#pragma unroll
            for (int p = 0; p < BWD_SPLIT; p++)
                g += g_pb[(size_t)p * NI * 64 + c * 64 + b];
            float xv = xin[c * 64 + b] - STEPF * g;
            int kb = c & 7;
            float thr = (kb == 0) ? 0.0f : ((kb == 7) ? 0.002f : 0.001f);
            float a = fabsf(xv) - thr;
            float r = (a > 0.0f) ? copysignf(a, xv) : 0.0f;
            xout[c * 64 + b] = r;
            tile[cl][b] = r;
        }
    }
    __syncthreads();
    {
        const int cl = t & 31, b0 = (t >> 5) * 8;
#pragma unroll
        for (int i = 0; i < 8; i++) {
            int b = b0 + i;
            float r = tile[cl][b];
            split_bf16(r, &g_x_hi[b * NI + c0 + cl], &g_x_lo[b * NI + c0 + cl]);
        }
    }
}

__global__ void write_out(const float* __restrict__ xin, float* __restrict__ out) {
    int idx = blockIdx.x * blockDim.x + threadIdx.x;
    if (idx >= BDIM * NI) return;
    int b = idx >> 12, c = idx & (NI - 1);
    out[idx] = xin[c * 64 + b];
}

// ---------------- mma.sync gemm ----------------
struct GemmArgs {
    const __nv_bfloat16 *Ahi, *Alo, *Bhi, *Blo;
    float* part;
    int Kdim;      // row stride (= total K)
    int Ctot;      // total output rows
    int kchunk;    // K per split-K chunk
};

// smem per stage (64B rows, XOR swizzle key (row>>1)&3):
//   A_hi [128][32] @0   A_lo @8192   B_hi [64][32] @16384   B_lo @20480
__device__ __forceinline__ void issue_stage(
    uint32_t sb, int buf, int tid, const GemmArgs& ga, int c0, int kk)
{
    uint32_t base = sb + buf * BUF_BYTES;
#pragma unroll
    for (int r = 0; r < 6; r++) {
        int q = tid + (r << 8);                // 1536 16B chunks per stage
        const __nv_bfloat16* gp;
        uint32_t tb;
        int row, cc;
        if (q < 1024) {                        // A: 128 rows x 4 chunks, hi | lo
            int half = q >> 9, qq = q & 511;
            row = qq >> 2; cc = qq & 3;
            gp = (half ? ga.Alo : ga.Ahi) + (size_t)(c0 + row) * ga.Kdim + kk + cc * 8;
            tb = base + half * 8192;
        } else {                               // B: 64 rows x 4 chunks, hi | lo
            int q2 = q - 1024;
            int half = q2 >> 8, qq = q2 & 255;
            row = qq >> 2; cc = qq & 3;
            gp = (half ? ga.Blo : ga.Bhi) + (size_t)row * ga.Kdim + kk + cc * 8;
            tb = base + 16384 + half * 4096;
        }
        uint32_t off = (uint32_t)((row << 6) | ((cc ^ ((row >> 1) & 3)) << 4));
        CP_ASYNC16(tb + off, gp);
    }
    CP_COMMIT();
}

__global__ __launch_bounds__(256, 2) void gemm_mma(GemmArgs ga) {
    extern __shared__ char smem[];
    uint32_t sb = smem_u32(smem);
    const int tid = threadIdx.x;
    const int c0 = blockIdx.x * MT;
    const int k0 = blockIdx.y * ga.kchunk;
    const int nst = ga.kchunk / KT;

    const int warp = tid >> 5, lane = tid & 31;
    const int wm = warp >> 1;          // m offset wm*32
    const int wn = warp & 1;           // n offset wn*32
    const int lrow = lane & 15;
    const int lhalf = lane >> 4;
    const int lsw = (lrow >> 1) & 3;   // swizzle key for 64B rows

    float acc[2][4][4];
#pragma unroll
    for (int am = 0; am < 2; am++)
#pragma unroll
        for (int ng = 0; ng < 4; ng++)
#pragma unroll
            for (int v = 0; v < 4; v++) acc[am][ng][v] = 0.0f;

    issue_stage(sb, 0, tid, ga, c0, k0);

    for (int s = 0; s < nst; s++) {
        if (s + 1 < nst) {
            issue_stage(sb, (s + 1) & 1, tid, ga, c0, k0 + (s + 1) * KT);
            CP_WAIT1();
        } else {
            CP_COMMIT();
            CP_WAIT0();
        }
        __syncthreads();

        uint32_t bufb = sb + (s & 1) * BUF_BYTES;
#pragma unroll
        for (int kk = 0; kk < 2; kk++) {       // two k16 steps per KT=32 stage
            uint32_t ksel = (uint32_t)((((kk << 1) | lhalf) ^ lsw) << 4);
            uint32_t ah[2][4], al[2][4], bh[2][4], bl[2][4];
#pragma unroll
            for (int am = 0; am < 2; am++) {
                uint32_t rb = (uint32_t)((wm * 32 + am * 16 + lrow) << 6) + ksel;
                ldsm4(ah[am], bufb + rb);
                ldsm4(al[am], bufb + 8192u + rb);
            }
#pragma unroll
            for (int bn = 0; bn < 2; bn++) {
                uint32_t rb = (uint32_t)((wn * 32 + bn * 16 + lrow) << 6) + ksel;
                ldsm4(bh[bn], bufb + 16384u + rb);
                ldsm4(bl[bn], bufb + 20480u + rb);
            }
#pragma unroll
            for (int am = 0; am < 2; am++)
#pragma unroll
                for (int ng = 0; ng < 4; ng++) {
                    int bn = ng >> 1, sel = ng & 1;
                    mma_bf16(acc[am][ng], ah[am], bh[bn][sel], bh[bn][sel + 2]);
                    mma_bf16(acc[am][ng], ah[am], bl[bn][sel], bl[bn][sel + 2]);
                    mma_bf16(acc[am][ng], al[am], bh[bn][sel], bh[bn][sel + 2]);
                }
        }
        __syncthreads();
    }

    const int qrow = lane >> 2, qcol2 = (lane & 3) << 1;
    float* po = ga.part + (size_t)blockIdx.y * ga.Ctot * 64;
#pragma unroll
    for (int am = 0; am < 2; am++)
#pragma unroll
        for (int ng = 0; ng < 4; ng++) {
            int c = c0 + wm * 32 + am * 16 + qrow;
            int col = wn * 32 + ng * 8 + qcol2;
            *reinterpret_cast<float2*>(&po[(size_t)c * 64 + col]) =
                make_float2(acc[am][ng][0], acc[am][ng][1]);
            *reinterpret_cast<float2*>(&po[(size_t)(c + 8) * 64 + col]) =
                make_float2(acc[am][ng][2], acc[am][ng][3]);
        }
}

// ---------------- host ----------------
extern "C" void kernel_launch(void* const* d_in, const int* in_sizes, int n_in,
                              void* d_out, int out_size)
{
    const float* y = (const float*)d_in[0];
    const float* A = (const float*)d_in[1];
    if (n_in >= 2 && in_sizes[0] > in_sizes[1]) {
        const float* t = y; y = A; A = t;
    }

    cudaFuncSetAttribute(gemm_mma, cudaFuncAttributeMaxDynamicSharedMemorySize, SMEM_TOTAL);

    __nv_bfloat16 *kfh, *kfl, *kbh, *kbl, *xh, *xl, *eh, *el;
    float *xA, *xB, *pf, *pb;
    cudaGetSymbolAddress((void**)&kfh, g_Kf_hi);
    cudaGetSymbolAddress((void**)&kfl, g_Kf_lo);
    cudaGetSymbolAddress((void**)&kbh, g_Kb_hi);
    cudaGetSymbolAddress((void**)&kbl, g_Kb_lo);
    cudaGetSymbolAddress((void**)&xh, g_x_hi);
    cudaGetSymbolAddress((void**)&xl, g_x_lo);
    cudaGetSymbolAddress((void**)&eh, g_e_hi);
    cudaGetSymbolAddress((void**)&el, g_e_lo);
    cudaGetSymbolAddress((void**)&xA, g_xA);
    cudaGetSymbolAddress((void**)&xB, g_xB);
    cudaGetSymbolAddress((void**)&pf, g_pf);
    cudaGetSymbolAddress((void**)&pb, g_pb);

    build_kf<<<(int)(((size_t)MI * NI + 255) / 256), 256>>>(A);
    build_kb<<<(int)(((size_t)NI * MI + 255) / 256), 256>>>(A);
    build_yT<<<(MI * BDIM + 255) / 256, 256>>>(y);
    init_x<<<(BDIM * NI + 255) / 256, 256>>>();

    GemmArgs gf;
    gf.Ahi = kfh; gf.Alo = kfl; gf.Bhi = xh; gf.Blo = xl;
    gf.part = pf; gf.Kdim = NI; gf.Ctot = MI; gf.kchunk = NI / FWD_SPLIT;   // 256
    GemmArgs gb;
    gb.Ahi = kbh; gb.Alo = kbl; gb.Bhi = eh; gb.Blo = el;
    gb.part = pb; gb.Kdim = MI; gb.Ctot = NI; gb.kchunk = MI / BWD_SPLIT;   // 256

    float* xcur = xA;
    float* xnxt = xB;
    for (int it = 0; it < NITER; it++) {
        gemm_mma<<<dim3(MI / MT, FWD_SPLIT), 256, SMEM_TOTAL>>>(gf);   // 16x16
        err_conv<<<MI / 32, 256>>>();
        gemm_mma<<<dim3(NI / MT, BWD_SPLIT), 256, SMEM_TOTAL>>>(gb);   // 32x8
        upd_x<<<NI / 32, 256>>>(xcur, xnxt);
        float* t = xcur; xcur = xnxt; xnxt = t;
    }
    write_out<<<(BDIM * NI + 255) / 256, 256>>>(xcur, (float*)d_out);
}

// round 5
// speedup vs baseline: 1.0914x; 1.0914x over previous
#include <cuda_runtime.h>
#include <cuda_bf16.h>
#include <cstdint>

// CliffordISTA — Round 5: R3 skeleton (KT=64, splits 8/4), 512-thread CTA (16 warps),
// warp tile 32x16, coalesced transpose elementwise kernels.
// out[c][b] = sum_k KT[c][k] * x[b][k];  v = hi + lo (bf16 split),
// D += Ahi*Bhi + Ahi*Blo + Alo*Bhi  (lo*lo dropped ~2^-16), fp32 accum.

#define BDIM 64
#define NB 8
#define MDIM 256
#define NDIM 512
#define NI 4096          // fwd inner dim / bwd out cols
#define MI 2048          // fwd out cols / bwd inner dim
#define NITER 50
#define STEPF 0.01f
#define KT 64            // K elems (bf16) per stage = 128B rows
#define MT 128           // M tile per CTA
#define FWD_SPLIT 8
#define BWD_SPLIT 4
#define NTHREADS 512

#define BUF_BYTES 49152  // per stage: A_hi 16K | A_lo 16K | B_hi 8K | B_lo 8K
#define SMEM_TOTAL (2 * BUF_BYTES)

// ---------------- device globals ----------------
__device__ __nv_bfloat16 g_Kf_hi[(size_t)MI * NI];   // KfT[c][k], c=m*8+kb, k=n*8+i
__device__ __nv_bfloat16 g_Kf_lo[(size_t)MI * NI];
__device__ __nv_bfloat16 g_Kb_hi[(size_t)NI * MI];   // KbT[c][k], c=n*8+kb, k=m*8+i
__device__ __nv_bfloat16 g_Kb_lo[(size_t)NI * MI];
__device__ __nv_bfloat16 g_x_hi[BDIM * NI];          // x[b][k]
__device__ __nv_bfloat16 g_x_lo[BDIM * NI];
__device__ __nv_bfloat16 g_e_hi[BDIM * MI];          // err[b][k]
__device__ __nv_bfloat16 g_e_lo[BDIM * MI];
__device__ float g_xA[NI * BDIM];                    // fp32 x state, [c][b]
__device__ float g_xB[NI * BDIM];
__device__ float g_yT[MI * BDIM];                    // y transposed [c][b]
__device__ float g_pf[(size_t)FWD_SPLIT * MI * BDIM];  // [s][c*64+b]
__device__ float g_pb[(size_t)BWD_SPLIT * NI * BDIM];

// ---------------- helpers ----------------
__device__ __forceinline__ uint32_t smem_u32(const void* p) {
    uint32_t a;
    asm("{ .reg .u64 t; cvta.to.shared.u64 t, %1; cvt.u32.u64 %0, t; }" : "=r"(a) : "l"(p));
    return a;
}

#define CP_ASYNC16(smem, gptr) \
    asm volatile("cp.async.cg.shared.global [%0], [%1], 16;" :: "r"(smem), "l"(gptr))
#define CP_COMMIT() asm volatile("cp.async.commit_group;" ::: "memory")
#define CP_WAIT1()  asm volatile("cp.async.wait_group 1;" ::: "memory")
#define CP_WAIT0()  asm volatile("cp.async.wait_group 0;" ::: "memory")

__device__ __forceinline__ void ldsm4(uint32_t* r, uint32_t addr) {
    asm volatile("ldmatrix.sync.aligned.m8n8.x4.shared.b16 {%0,%1,%2,%3}, [%4];"
                 : "=r"(r[0]), "=r"(r[1]), "=r"(r[2]), "=r"(r[3]) : "r"(addr));
}

__device__ __forceinline__ void mma_bf16(float* c, const uint32_t* a, uint32_t b0, uint32_t b1) {
    asm volatile(
        "mma.sync.aligned.m16n8k16.row.col.f32.bf16.bf16.f32 "
        "{%0,%1,%2,%3}, {%4,%5,%6,%7}, {%8,%9}, {%0,%1,%2,%3};"
        : "+f"(c[0]), "+f"(c[1]), "+f"(c[2]), "+f"(c[3])
        : "r"(a[0]), "r"(a[1]), "r"(a[2]), "r"(a[3]), "r"(b0), "r"(b1));
}

__device__ __forceinline__ float csign(int i, int j) {
    int cnt = __popc((i >> 1) & j) + __popc((i >> 2) & j);
    return (cnt & 1) ? -1.0f : 1.0f;
}

__device__ __forceinline__ void split_bf16(float v, __nv_bfloat16* hi, __nv_bfloat16* lo) {
    __nv_bfloat16 h = __float2bfloat16(v);
    *hi = h;
    *lo = __float2bfloat16(v - __bfloat162float(h));
}

// ---------------- build / elementwise ----------------
__global__ void build_kf(const float* __restrict__ A) {
    size_t idx = (size_t)blockIdx.x * blockDim.x + threadIdx.x;
    if (idx >= (size_t)MI * NI) return;
    int c = (int)(idx >> 12), k = (int)(idx & (NI - 1));
    int m = c >> 3, kb = c & 7, n = k >> 3, i = k & 7, j = i ^ kb;
    float v = csign(i, j) * A[(m * NDIM + n) * NB + j];
    split_bf16(v, &g_Kf_hi[idx], &g_Kf_lo[idx]);
}

__global__ void build_kb(const float* __restrict__ A) {
    size_t idx = (size_t)blockIdx.x * blockDim.x + threadIdx.x;
    if (idx >= (size_t)NI * MI) return;
    int c = (int)(idx >> 11), k = (int)(idx & (MI - 1));
    int n = c >> 3, kb = c & 7, m = k >> 3, i = k & 7, j = i ^ kb;
    float rv = (__popc(j) >= 2) ? -1.0f : 1.0f;
    float v = csign(i, j) * rv * A[(m * NDIM + n) * NB + j];
    split_bf16(v, &g_Kb_hi[idx], &g_Kb_lo[idx]);
}

__global__ void build_yT(const float* __restrict__ y) {
    int idx = blockIdx.x * blockDim.x + threadIdx.x;
    if (idx >= MI * BDIM) return;
    int c = idx >> 6, b = idx & 63;
    g_yT[idx] = y[b * MI + c];
}

__global__ void init_x() {
    int idx = blockIdx.x * blockDim.x + threadIdx.x;
    if (idx >= BDIM * NI) return;
    g_xA[idx] = 0.0f;
    g_x_hi[idx] = __float2bfloat16(0.0f);
    g_x_lo[idx] = __float2bfloat16(0.0f);
}

// err_conv: block handles 32 c-rows x 64 b. Coalesced partial reads, smem
// transpose, coalesced bf16 writes to e[b][c].
__global__ __launch_bounds__(256) void err_conv() {
    __shared__ float tile[32][65];
    const int c0 = blockIdx.x * 32;
    const int t = threadIdx.x;
    {
        const int b = t & 63, cl0 = t >> 6;
#pragma unroll
        for (int i = 0; i < 8; i++) {
            int cl = cl0 + i * 4;
            int c = c0 + cl;
            float s = 0.0f;
#pragma unroll
            for (int p = 0; p < FWD_SPLIT; p++)
                s += g_pf[(size_t)p * MI * 64 + c * 64 + b];
            tile[cl][b] = s - g_yT[c * 64 + b];
        }
    }
    __syncthreads();
    {
        const int cl = t & 31, b0 = (t >> 5) * 8;
#pragma unroll
        for (int i = 0; i < 8; i++) {
            int b = b0 + i;
            float e = tile[cl][b];
            split_bf16(e, &g_e_hi[b * MI + c0 + cl], &g_e_lo[b * MI + c0 + cl]);
        }
    }
}

__global__ __launch_bounds__(256) void upd_x(const float* __restrict__ xin,
                                             float* __restrict__ xout) {
    __shared__ float tile[32][65];
    const int c0 = blockIdx.x * 32;
    const int t = threadIdx.x;
    {
        const int b = t & 63, cl0 = t >> 6;
#pragma unroll
        for (int i = 0; i < 8; i++) {
            int cl = cl0 + i * 4;
            int c = c0 + cl;
            float g = 0.0f;
#pragma unroll
            for (int p = 0; p < BWD_SPLIT; p++)
                g += g_pb[(size_t)p * NI * 64 + c * 64 + b];
            float xv = xin[c * 64 + b] - STEPF * g;
            int kb = c & 7;
            float thr = (kb == 0) ? 0.0f : ((kb == 7) ? 0.002f : 0.001f);
            float a = fabsf(xv) - thr;
            float r = (a > 0.0f) ? copysignf(a, xv) : 0.0f;
            xout[c * 64 + b] = r;
            tile[cl][b] = r;
        }
    }
    __syncthreads();
    {
        const int cl = t & 31, b0 = (t >> 5) * 8;
#pragma unroll
        for (int i = 0; i < 8; i++) {
            int b = b0 + i;
            float r = tile[cl][b];
            split_bf16(r, &g_x_hi[b * NI + c0 + cl], &g_x_lo[b * NI + c0 + cl]);
        }
    }
}

__global__ void write_out(const float* __restrict__ xin, float* __restrict__ out) {
    int idx = blockIdx.x * blockDim.x + threadIdx.x;
    if (idx >= BDIM * NI) return;
    int b = idx >> 12, c = idx & (NI - 1);
    out[idx] = xin[c * 64 + b];
}

// ---------------- mma.sync gemm ----------------
struct GemmArgs {
    const __nv_bfloat16 *Ahi, *Alo, *Bhi, *Blo;
    float* part;
    int Kdim;      // row stride (= total K)
    int Ctot;      // total output rows
    int kchunk;    // K per split-K chunk
};

// smem per stage (128B rows, XOR swizzle key row&7):
//   A_hi [128][64] @0   A_lo @16384   B_hi [64][64] @32768   B_lo @40960
__device__ __forceinline__ void issue_stage(
    uint32_t sb, int buf, int tid, const GemmArgs& ga, int c0, int kk)
{
    uint32_t base = sb + buf * BUF_BYTES;
#pragma unroll
    for (int r = 0; r < 6; r++) {
        int q = tid + (r << 9);                // 3072 16B chunks per stage
        const __nv_bfloat16* gp;
        uint32_t tb;
        int row, cc;
        if (q < 2048) {                        // A: 128 rows x 8 chunks, hi | lo
            int half = q >> 10, qq = q & 1023;
            row = qq >> 3; cc = qq & 7;
            gp = (half ? ga.Alo : ga.Ahi) + (size_t)(c0 + row) * ga.Kdim + kk + cc * 8;
            tb = base + half * 16384;
        } else {                               // B: 64 rows x 8 chunks, hi | lo
            int q2 = q - 2048;
            int half = q2 >> 9, qq = q2 & 511;
            row = qq >> 3; cc = qq & 7;
            gp = (half ? ga.Blo : ga.Bhi) + (size_t)row * ga.Kdim + kk + cc * 8;
            tb = base + 32768 + half * 8192;
        }
        uint32_t off = (uint32_t)((row << 7) | ((cc ^ (row & 7)) << 4));
        CP_ASYNC16(tb + off, gp);
    }
    CP_COMMIT();
}

__global__ __launch_bounds__(NTHREADS, 1) void gemm_mma(GemmArgs ga) {
    extern __shared__ char smem[];
    uint32_t sb = smem_u32(smem);
    const int tid = threadIdx.x;
    const int c0 = blockIdx.x * MT;
    const int k0 = blockIdx.y * ga.kchunk;
    const int nst = ga.kchunk / KT;

    const int warp = tid >> 5, lane = tid & 31;
    const int wm = warp >> 2;          // 0..3 -> m offset wm*32
    const int wn = warp & 3;           // 0..3 -> n offset wn*16
    const int lrow = lane & 15;
    const int lhalf = lane >> 4;
    const int lsw = lrow & 7;          // swizzle key for 128B rows

    float acc[2][2][4];
#pragma unroll
    for (int am = 0; am < 2; am++)
#pragma unroll
        for (int sel = 0; sel < 2; sel++)
#pragma unroll
            for (int v = 0; v < 4; v++) acc[am][sel][v] = 0.0f;

    issue_stage(sb, 0, tid, ga, c0, k0);

    for (int s = 0; s < nst; s++) {
        if (s + 1 < nst) {
            issue_stage(sb, (s + 1) & 1, tid, ga, c0, k0 + (s + 1) * KT);
            CP_WAIT1();
        } else {
            CP_COMMIT();
            CP_WAIT0();
        }
        __syncthreads();

        uint32_t bufb = sb + (s & 1) * BUF_BYTES;
#pragma unroll
        for (int kk = 0; kk < 4; kk++) {       // four k16 steps per KT=64 stage
            uint32_t ksel = (uint32_t)((((kk << 1) | lhalf) ^ lsw) << 4);
            uint32_t ah[2][4], al[2][4], bh[4], bl[4];
#pragma unroll
            for (int am = 0; am < 2; am++) {
                uint32_t rb = (uint32_t)((wm * 32 + am * 16 + lrow) << 7) + ksel;
                ldsm4(ah[am], bufb + rb);
                ldsm4(al[am], bufb + 16384u + rb);
            }
            {
                uint32_t rb = (uint32_t)((wn * 16 + lrow) << 7) + ksel;
                ldsm4(bh, bufb + 32768u + rb);
                ldsm4(bl, bufb + 40960u + rb);
            }
#pragma unroll
            for (int am = 0; am < 2; am++)
#pragma unroll
                for (int sel = 0; sel < 2; sel++) {
                    mma_bf16(acc[am][sel], ah[am], bh[sel], bh[sel + 2]);
                    mma_bf16(acc[am][sel], ah[am], bl[sel], bl[sel + 2]);
                    mma_bf16(acc[am][sel], al[am], bh[sel], bh[sel + 2]);
                }
        }
        __syncthreads();
    }

    const int qrow = lane >> 2, qcol2 = (lane & 3) << 1;
    float* po = ga.part + (size_t)blockIdx.y * ga.Ctot * 64;
#pragma unroll
    for (int am = 0; am < 2; am++)
#pragma unroll
        for (int sel = 0; sel < 2; sel++) {
            int c = c0 + wm * 32 + am * 16 + qrow;
            int col = wn * 16 + sel * 8 + qcol2;
            *reinterpret_cast<float2*>(&po[(size_t)c * 64 + col]) =
                make_float2(acc[am][sel][0], acc[am][sel][1]);
            *reinterpret_cast<float2*>(&po[(size_t)(c + 8) * 64 + col]) =
                make_float2(acc[am][sel][2], acc[am][sel][3]);
        }
}

// ---------------- host ----------------
extern "C" void kernel_launch(void* const* d_in, const int* in_sizes, int n_in,
                              void* d_out, int out_size)
{
    const float* y = (const float*)d_in[0];
    const float* A = (const float*)d_in[1];
    if (n_in >= 2 && in_sizes[0] > in_sizes[1]) {
        const float* t = y; y = A; A = t;
    }

    cudaFuncSetAttribute(gemm_mma, cudaFuncAttributeMaxDynamicSharedMemorySize, SMEM_TOTAL);

    __nv_bfloat16 *kfh, *kfl, *kbh, *kbl, *xh, *xl, *eh, *el;
    float *xA, *xB, *pf, *pb;
    cudaGetSymbolAddress((void**)&kfh, g_Kf_hi);
    cudaGetSymbolAddress((void**)&kfl, g_Kf_lo);
    cudaGetSymbolAddress((void**)&kbh, g_Kb_hi);
    cudaGetSymbolAddress((void**)&kbl, g_Kb_lo);
    cudaGetSymbolAddress((void**)&xh, g_x_hi);
    cudaGetSymbolAddress((void**)&xl, g_x_lo);
    cudaGetSymbolAddress((void**)&eh, g_e_hi);
    cudaGetSymbolAddress((void**)&el, g_e_lo);
    cudaGetSymbolAddress((void**)&xA, g_xA);
    cudaGetSymbolAddress((void**)&xB, g_xB);
    cudaGetSymbolAddress((void**)&pf, g_pf);
    cudaGetSymbolAddress((void**)&pb, g_pb);

    build_kf<<<(int)(((size_t)MI * NI + 255) / 256), 256>>>(A);
    build_kb<<<(int)(((size_t)NI * MI + 255) / 256), 256>>>(A);
    build_yT<<<(MI * BDIM + 255) / 256, 256>>>(y);
    init_x<<<(BDIM * NI + 255) / 256, 256>>>();

    GemmArgs gf;
    gf.Ahi = kfh; gf.Alo = kfl; gf.Bhi = xh; gf.Blo = xl;
    gf.part = pf; gf.Kdim = NI; gf.Ctot = MI; gf.kchunk = NI / FWD_SPLIT;   // 512
    GemmArgs gb;
    gb.Ahi = kbh; gb.Alo = kbl; gb.Bhi = eh; gb.Blo = el;
    gb.part = pb; gb.Kdim = MI; gb.Ctot = NI; gb.kchunk = MI / BWD_SPLIT;   // 512

    float* xcur = xA;
    float* xnxt = xB;
    for (int it = 0; it < NITER; it++) {
        gemm_mma<<<dim3(MI / MT, FWD_SPLIT), NTHREADS, SMEM_TOTAL>>>(gf);  // 16x8
        err_conv<<<MI / 32, 256>>>();
        gemm_mma<<<dim3(NI / MT, BWD_SPLIT), NTHREADS, SMEM_TOTAL>>>(gb);  // 32x4
        upd_x<<<NI / 32, 256>>>(xcur, xnxt);
        float* t = xcur; xcur = xnxt; xnxt = t;
    }
    write_out<<<(BDIM * NI + 255) / 256, 256>>>(xcur, (float*)d_out);
}

// round 6
// speedup vs baseline: 1.7531x; 1.6063x over previous
#include <cuda_runtime.h>
#include <cuda_fp16.h>
#include <cstdint>

// CliffordISTA — Round 6: fp16 single-product mma.sync GEMM (3x fewer mma than
// the bf16 hi/lo 3-product scheme; fp32 accumulate keeps rel_err ~2e-4 << 1e-3).
// out[c][b] = sum_k KT[c][k] * x[b][k]
// Skeleton identical to R5: KT=64 double-buffered cp.async, 512-thread CTA,
// warp tile 32x16, splits 8/4 (128 CTAs per gemm), deterministic reduces.

#define BDIM 64
#define NB 8
#define MDIM 256
#define NDIM 512
#define NI 4096          // fwd inner dim / bwd out cols
#define MI 2048          // fwd out cols / bwd inner dim
#define NITER 50
#define STEPF 0.01f
#define KT 64            // K elems (fp16) per stage = 128B rows
#define MT 128           // M tile per CTA
#define FWD_SPLIT 8
#define BWD_SPLIT 4
#define NTHREADS 512

#define BUF_BYTES 24576  // per stage: A 16K | B 8K
#define SMEM_TOTAL (2 * BUF_BYTES)

// ---------------- device globals ----------------
__device__ __half g_Kf[(size_t)MI * NI];   // KfT[c][k], c=m*8+kb, k=n*8+i
__device__ __half g_Kb[(size_t)NI * MI];   // KbT[c][k], c=n*8+kb, k=m*8+i
__device__ __half g_x[BDIM * NI];          // x[b][k]
__device__ __half g_e[BDIM * MI];          // err[b][k]
__device__ float g_xA[NI * BDIM];          // fp32 x state, [c][b]
__device__ float g_xB[NI * BDIM];
__device__ float g_yT[MI * BDIM];          // y transposed [c][b]
__device__ float g_pf[(size_t)FWD_SPLIT * MI * BDIM];  // [s][c*64+b]
__device__ float g_pb[(size_t)BWD_SPLIT * NI * BDIM];

// ---------------- helpers ----------------
__device__ __forceinline__ uint32_t smem_u32(const void* p) {
    uint32_t a;
    asm("{ .reg .u64 t; cvta.to.shared.u64 t, %1; cvt.u32.u64 %0, t; }" : "=r"(a) : "l"(p));
    return a;
}

#define CP_ASYNC16(smem, gptr) \
    asm volatile("cp.async.cg.shared.global [%0], [%1], 16;" :: "r"(smem), "l"(gptr))
#define CP_COMMIT() asm volatile("cp.async.commit_group;" ::: "memory")
#define CP_WAIT1()  asm volatile("cp.async.wait_group 1;" ::: "memory")
#define CP_WAIT0()  asm volatile("cp.async.wait_group 0;" ::: "memory")

__device__ __forceinline__ void ldsm4(uint32_t* r, uint32_t addr) {
    asm volatile("ldmatrix.sync.aligned.m8n8.x4.shared.b16 {%0,%1,%2,%3}, [%4];"
                 : "=r"(r[0]), "=r"(r[1]), "=r"(r[2]), "=r"(r[3]) : "r"(addr));
}

__device__ __forceinline__ void mma_fp16(float* c, const uint32_t* a, uint32_t b0, uint32_t b1) {
    asm volatile(
        "mma.sync.aligned.m16n8k16.row.col.f32.f16.f16.f32 "
        "{%0,%1,%2,%3}, {%4,%5,%6,%7}, {%8,%9}, {%0,%1,%2,%3};"
        : "+f"(c[0]), "+f"(c[1]), "+f"(c[2]), "+f"(c[3])
        : "r"(a[0]), "r"(a[1]), "r"(a[2]), "r"(a[3]), "r"(b0), "r"(b1));
}

__device__ __forceinline__ float csign(int i, int j) {
    int cnt = __popc((i >> 1) & j) + __popc((i >> 2) & j);
    return (cnt & 1) ? -1.0f : 1.0f;
}

// ---------------- build / elementwise ----------------
__global__ void build_kf(const float* __restrict__ A) {
    size_t idx = (size_t)blockIdx.x * blockDim.x + threadIdx.x;
    if (idx >= (size_t)MI * NI) return;
    int c = (int)(idx >> 12), k = (int)(idx & (NI - 1));
    int m = c >> 3, kb = c & 7, n = k >> 3, i = k & 7, j = i ^ kb;
    g_Kf[idx] = __float2half(csign(i, j) * A[(m * NDIM + n) * NB + j]);
}

__global__ void build_kb(const float* __restrict__ A) {
    size_t idx = (size_t)blockIdx.x * blockDim.x + threadIdx.x;
    if (idx >= (size_t)NI * MI) return;
    int c = (int)(idx >> 11), k = (int)(idx & (MI - 1));
    int n = c >> 3, kb = c & 7, m = k >> 3, i = k & 7, j = i ^ kb;
    float rv = (__popc(j) >= 2) ? -1.0f : 1.0f;
    g_Kb[idx] = __float2half(csign(i, j) * rv * A[(m * NDIM + n) * NB + j]);
}

__global__ void build_yT(const float* __restrict__ y) {
    int idx = blockIdx.x * blockDim.x + threadIdx.x;
    if (idx >= MI * BDIM) return;
    int c = idx >> 6, b = idx & 63;
    g_yT[idx] = y[b * MI + c];
}

__global__ void init_x() {
    int idx = blockIdx.x * blockDim.x + threadIdx.x;
    if (idx >= BDIM * NI) return;
    g_xA[idx] = 0.0f;
    g_x[idx] = __float2half(0.0f);
}

// err_conv: block handles 32 c-rows x 64 b. Coalesced partial reads, smem
// transpose, coalesced fp16 writes to e[b][c].
__global__ __launch_bounds__(256) void err_conv() {
    __shared__ float tile[32][65];
    const int c0 = blockIdx.x * 32;
    const int t = threadIdx.x;
    {
        const int b = t & 63, cl0 = t >> 6;
#pragma unroll
        for (int i = 0; i < 8; i++) {
            int cl = cl0 + i * 4;
            int c = c0 + cl;
            float s = 0.0f;
#pragma unroll
            for (int p = 0; p < FWD_SPLIT; p++)
                s += g_pf[(size_t)p * MI * 64 + c * 64 + b];
            tile[cl][b] = s - g_yT[c * 64 + b];
        }
    }
    __syncthreads();
    {
        const int cl = t & 31, b0 = (t >> 5) * 8;
#pragma unroll
        for (int i = 0; i < 8; i++) {
            int b = b0 + i;
            g_e[b * MI + c0 + cl] = __float2half(tile[cl][b]);
        }
    }
}

__global__ __launch_bounds__(256) void upd_x(const float* __restrict__ xin,
                                             float* __restrict__ xout) {
    __shared__ float tile[32][65];
    const int c0 = blockIdx.x * 32;
    const int t = threadIdx.x;
    {
        const int b = t & 63, cl0 = t >> 6;
#pragma unroll
        for (int i = 0; i < 8; i++) {
            int cl = cl0 + i * 4;
            int c = c0 + cl;
            float g = 0.0f;
#pragma unroll
            for (int p = 0; p < BWD_SPLIT; p++)
                g += g_pb[(size_t)p * NI * 64 + c * 64 + b];
            float xv = xin[c * 64 + b] - STEPF * g;
            int kb = c & 7;
            float thr = (kb == 0) ? 0.0f : ((kb == 7) ? 0.002f : 0.001f);
            float a = fabsf(xv) - thr;
            float r = (a > 0.0f) ? copysignf(a, xv) : 0.0f;
            xout[c * 64 + b] = r;
            tile[cl][b] = r;
        }
    }
    __syncthreads();
    {
        const int cl = t & 31, b0 = (t >> 5) * 8;
#pragma unroll
        for (int i = 0; i < 8; i++) {
            int b = b0 + i;
            g_x[b * NI + c0 + cl] = __float2half(tile[cl][b]);
        }
    }
}

__global__ void write_out(const float* __restrict__ xin, float* __restrict__ out) {
    int idx = blockIdx.x * blockDim.x + threadIdx.x;
    if (idx >= BDIM * NI) return;
    int b = idx >> 12, c = idx & (NI - 1);
    out[idx] = xin[c * 64 + b];
}

// ---------------- mma.sync gemm ----------------
struct GemmArgs {
    const __half *Am, *Bm;
    float* part;
    int Kdim;      // row stride (= total K)
    int Ctot;      // total output rows
    int kchunk;    // K per split-K chunk
};

// smem per stage (128B rows, XOR swizzle key row&7):
//   A [128][64] fp16 @0    B [64][64] fp16 @16384
__device__ __forceinline__ void issue_stage(
    uint32_t sb, int buf, int tid, const GemmArgs& ga, int c0, int kk)
{
    uint32_t base = sb + buf * BUF_BYTES;
#pragma unroll
    for (int r = 0; r < 3; r++) {
        int q = tid + (r << 9);                // 1536 16B chunks per stage
        const __half* gp;
        uint32_t tb;
        int row, cc;
        if (q < 1024) {                        // A: 128 rows x 8 chunks
            row = q >> 3; cc = q & 7;
            gp = ga.Am + (size_t)(c0 + row) * ga.Kdim + kk + cc * 8;
            tb = base;
        } else {                               // B: 64 rows x 8 chunks
            int q2 = q - 1024;
            row = q2 >> 3; cc = q2 & 7;
            gp = ga.Bm + (size_t)row * ga.Kdim + kk + cc * 8;
            tb = base + 16384;
        }
        uint32_t off = (uint32_t)((row << 7) | ((cc ^ (row & 7)) << 4));
        CP_ASYNC16(tb + off, gp);
    }
    CP_COMMIT();
}

__global__ __launch_bounds__(NTHREADS, 1) void gemm_mma(GemmArgs ga) {
    extern __shared__ char smem[];
    uint32_t sb = smem_u32(smem);
    const int tid = threadIdx.x;
    const int c0 = blockIdx.x * MT;
    const int k0 = blockIdx.y * ga.kchunk;
    const int nst = ga.kchunk / KT;

    const int warp = tid >> 5, lane = tid & 31;
    const int wm = warp >> 2;          // 0..3 -> m offset wm*32
    const int wn = warp & 3;           // 0..3 -> n offset wn*16
    const int lrow = lane & 15;
    const int lhalf = lane >> 4;
    const int lsw = lrow & 7;          // swizzle key for 128B rows

    float acc[2][2][4];
#pragma unroll
    for (int am = 0; am < 2; am++)
#pragma unroll
        for (int sel = 0; sel < 2; sel++)
#pragma unroll
            for (int v = 0; v < 4; v++) acc[am][sel][v] = 0.0f;

    issue_stage(sb, 0, tid, ga, c0, k0);

    for (int s = 0; s < nst; s++) {
        if (s + 1 < nst) {
            issue_stage(sb, (s + 1) & 1, tid, ga, c0, k0 + (s + 1) * KT);
            CP_WAIT1();
        } else {
            CP_COMMIT();
            CP_WAIT0();
        }
        __syncthreads();

        uint32_t bufb = sb + (s & 1) * BUF_BYTES;
#pragma unroll
        for (int kk = 0; kk < 4; kk++) {       // four k16 steps per KT=64 stage
            uint32_t ksel = (uint32_t)((((kk << 1) | lhalf) ^ lsw) << 4);
            uint32_t ah[2][4], bb[4];
#pragma unroll
            for (int am = 0; am < 2; am++) {
                uint32_t rb = (uint32_t)((wm * 32 + am * 16 + lrow) << 7) + ksel;
                ldsm4(ah[am], bufb + rb);
            }
            {
                uint32_t rb = (uint32_t)((wn * 16 + lrow) << 7) + ksel;
                ldsm4(bb, bufb + 16384u + rb);
            }
#pragma unroll
            for (int am = 0; am < 2; am++)
#pragma unroll
                for (int sel = 0; sel < 2; sel++)
                    mma_fp16(acc[am][sel], ah[am], bb[sel], bb[sel + 2]);
        }
        __syncthreads();
    }

    const int qrow = lane >> 2, qcol2 = (lane & 3) << 1;
    float* po = ga.part + (size_t)blockIdx.y * ga.Ctot * 64;
#pragma unroll
    for (int am = 0; am < 2; am++)
#pragma unroll
        for (int sel = 0; sel < 2; sel++) {
            int c = c0 + wm * 32 + am * 16 + qrow;
            int col = wn * 16 + sel * 8 + qcol2;
            *reinterpret_cast<float2*>(&po[(size_t)c * 64 + col]) =
                make_float2(acc[am][sel][0], acc[am][sel][1]);
            *reinterpret_cast<float2*>(&po[(size_t)(c + 8) * 64 + col]) =
                make_float2(acc[am][sel][2], acc[am][sel][3]);
        }
}

// ---------------- host ----------------
extern "C" void kernel_launch(void* const* d_in, const int* in_sizes, int n_in,
                              void* d_out, int out_size)
{
    const float* y = (const float*)d_in[0];
    const float* A = (const float*)d_in[1];
    if (n_in >= 2 && in_sizes[0] > in_sizes[1]) {
        const float* t = y; y = A; A = t;
    }

    cudaFuncSetAttribute(gemm_mma, cudaFuncAttributeMaxDynamicSharedMemorySize, SMEM_TOTAL);

    __half *kf, *kb, *xh, *eh;
    float *xA, *xB, *pf, *pb;
    cudaGetSymbolAddress((void**)&kf, g_Kf);
    cudaGetSymbolAddress((void**)&kb, g_Kb);
    cudaGetSymbolAddress((void**)&xh, g_x);
    cudaGetSymbolAddress((void**)&eh, g_e);
    cudaGetSymbolAddress((void**)&xA, g_xA);
    cudaGetSymbolAddress((void**)&xB, g_xB);
    cudaGetSymbolAddress((void**)&pf, g_pf);
    cudaGetSymbolAddress((void**)&pb, g_pb);

    build_kf<<<(int)(((size_t)MI * NI + 255) / 256), 256>>>(A);
    build_kb<<<(int)(((size_t)NI * MI + 255) / 256), 256>>>(A);
    build_yT<<<(MI * BDIM + 255) / 256, 256>>>(y);
    init_x<<<(BDIM * NI + 255) / 256, 256>>>();

    GemmArgs gf;
    gf.Am = kf; gf.Bm = xh;
    gf.part = pf; gf.Kdim = NI; gf.Ctot = MI; gf.kchunk = NI / FWD_SPLIT;   // 512
    GemmArgs gb;
    gb.Am = kb; gb.Bm = eh;
    gb.part = pb; gb.Kdim = MI; gb.Ctot = NI; gb.kchunk = MI / BWD_SPLIT;   // 512

    float* xcur = xA;
    float* xnxt = xB;
    for (int it = 0; it < NITER; it++) {
        gemm_mma<<<dim3(MI / MT, FWD_SPLIT), NTHREADS, SMEM_TOTAL>>>(gf);  // 16x8
        err_conv<<<MI / 32, 256>>>();
        gemm_mma<<<dim3(NI / MT, BWD_SPLIT), NTHREADS, SMEM_TOTAL>>>(gb);  // 32x4
        upd_x<<<NI / 32, 256>>>(xcur, xnxt);
        float* t = xcur; xcur = xnxt; xnxt = t;
    }
    write_out<<<(BDIM * NI + 255) / 256, 256>>>(xcur, (float*)d_out);
}

// round 7
// speedup vs baseline: 1.8902x; 1.0782x over previous
#include <cuda_runtime.h>
#include <cuda_fp16.h>
#include <cstdint>

// CliffordISTA — Round 7: single persistent kernel (all 50 iterations),
// software grid barriers replace ~200 kernel launches.
// fp16 single-product mma.sync GEMM, fp32 accum (rel_err ~2e-4).

#define BDIM 64
#define NB 8
#define MDIM 256
#define NDIM 512
#define NI 4096
#define MI 2048
#define NITER 50
#define STEPF 0.01f
#define KT 64
#define MT 128
#define FWD_SPLIT 8
#define BWD_SPLIT 4
#define NTHREADS 512
#define GRID 128

#define BUF_BYTES 24576  // per stage: A 16K | B 8K
#define SMEM_TOTAL (2 * BUF_BYTES)

// ---------------- device globals ----------------
__device__ __half g_Kf[(size_t)MI * NI];   // KfT[c][k], c=m*8+kb, k=n*8+i
__device__ __half g_Kb[(size_t)NI * MI];   // KbT[c][k], c=n*8+kb, k=m*8+i
__device__ __half g_x[BDIM * NI];          // x[b][k]
__device__ __half g_e[BDIM * MI];          // err[b][k]
__device__ float g_xA[NI * BDIM];          // fp32 x state, [c][b]
__device__ float g_xB[NI * BDIM];
__device__ float g_yT[MI * BDIM];          // y transposed [c][b]
__device__ float g_pf[(size_t)FWD_SPLIT * MI * BDIM];
__device__ float g_pb[(size_t)BWD_SPLIT * NI * BDIM];

// grid barrier state (monotonic; zeroed by init each launch)
__device__ unsigned g_sub[8 * 32];         // 8 sub-counters, 128B apart
__device__ unsigned g_root;

// ---------------- helpers ----------------
__device__ __forceinline__ uint32_t smem_u32(const void* p) {
    uint32_t a;
    asm("{ .reg .u64 t; cvta.to.shared.u64 t, %1; cvt.u32.u64 %0, t; }" : "=r"(a) : "l"(p));
    return a;
}

#define CP_ASYNC16(smem, gptr) \
    asm volatile("cp.async.cg.shared.global [%0], [%1], 16;" :: "r"(smem), "l"(gptr))
#define CP_COMMIT() asm volatile("cp.async.commit_group;" ::: "memory")
#define CP_WAIT1()  asm volatile("cp.async.wait_group 1;" ::: "memory")
#define CP_WAIT0()  asm volatile("cp.async.wait_group 0;" ::: "memory")

__device__ __forceinline__ void ldsm4(uint32_t* r, uint32_t addr) {
    asm volatile("ldmatrix.sync.aligned.m8n8.x4.shared.b16 {%0,%1,%2,%3}, [%4];"
                 : "=r"(r[0]), "=r"(r[1]), "=r"(r[2]), "=r"(r[3]) : "r"(addr));
}

__device__ __forceinline__ void mma_fp16(float* c, const uint32_t* a, uint32_t b0, uint32_t b1) {
    asm volatile(
        "mma.sync.aligned.m16n8k16.row.col.f32.f16.f16.f32 "
        "{%0,%1,%2,%3}, {%4,%5,%6,%7}, {%8,%9}, {%0,%1,%2,%3};"
        : "+f"(c[0]), "+f"(c[1]), "+f"(c[2]), "+f"(c[3])
        : "r"(a[0]), "r"(a[1]), "r"(a[2]), "r"(a[3]), "r"(b0), "r"(b1));
}

__device__ __forceinline__ float csign(int i, int j) {
    int cnt = __popc((i >> 1) & j) + __popc((i >> 2) & j);
    return (cnt & 1) ? -1.0f : 1.0f;
}

// grid barrier: 8-way sub-counters -> root; monotonic targets (no resets mid-run)
__device__ __forceinline__ void grid_bar(unsigned nb, int cta) {
    __syncthreads();
    if (threadIdx.x == 0) {
        __threadfence();
        unsigned prev = atomicAdd(&g_sub[(cta & 7) * 32], 1u);
        if (prev + 1u == 16u * nb)
            atomicAdd(&g_root, 1u);
        unsigned target = 8u * nb, v;
        do {
            asm volatile("ld.volatile.global.u32 %0, [%1];" : "=r"(v) : "l"(&g_root));
        } while ((int)(v - target) < 0);
        __threadfence();
    }
    __syncthreads();
}

// ---------------- build / init kernels ----------------
__global__ void build_kf(const float* __restrict__ A) {
    size_t idx = (size_t)blockIdx.x * blockDim.x + threadIdx.x;
    if (idx >= (size_t)MI * NI) return;
    int c = (int)(idx >> 12), k = (int)(idx & (NI - 1));
    int m = c >> 3, kb = c & 7, n = k >> 3, i = k & 7, j = i ^ kb;
    g_Kf[idx] = __float2half(csign(i, j) * A[(m * NDIM + n) * NB + j]);
}

__global__ void build_kb(const float* __restrict__ A) {
    size_t idx = (size_t)blockIdx.x * blockDim.x + threadIdx.x;
    if (idx >= (size_t)NI * MI) return;
    int c = (int)(idx >> 11), k = (int)(idx & (MI - 1));
    int n = c >> 3, kb = c & 7, m = k >> 3, i = k & 7, j = i ^ kb;
    float rv = (__popc(j) >= 2) ? -1.0f : 1.0f;
    g_Kb[idx] = __float2half(csign(i, j) * rv * A[(m * NDIM + n) * NB + j]);
}

__global__ void build_yT(const float* __restrict__ y) {
    int idx = blockIdx.x * blockDim.x + threadIdx.x;
    if (idx >= MI * BDIM) return;
    int c = idx >> 6, b = idx & 63;
    g_yT[idx] = y[b * MI + c];
}

__global__ void init_x() {
    int idx = blockIdx.x * blockDim.x + threadIdx.x;
    if (idx < BDIM * NI) {
        g_xA[idx] = 0.0f;
        g_x[idx] = __float2half(0.0f);
    }
    if (idx < 8 * 32) g_sub[idx] = 0u;
    if (idx == 0) g_root = 0u;
}

// ---------------- gemm phase (device) ----------------
__device__ __forceinline__ void issue_stage(
    uint32_t sb, int buf, int tid, const __half* Am, const __half* Bm,
    int Kdim, int c0, int kk)
{
    uint32_t base = sb + buf * BUF_BYTES;
#pragma unroll
    for (int r = 0; r < 3; r++) {
        int q = tid + (r << 9);                // 1536 16B chunks per stage
        const __half* gp;
        uint32_t tb;
        int row, cc;
        if (q < 1024) {                        // A: 128 rows x 8 chunks
            row = q >> 3; cc = q & 7;
            gp = Am + (size_t)(c0 + row) * Kdim + kk + cc * 8;
            tb = base;
        } else {                               // B: 64 rows x 8 chunks
            int q2 = q - 1024;
            row = q2 >> 3; cc = q2 & 7;
            gp = Bm + (size_t)row * Kdim + kk + cc * 8;
            tb = base + 16384;
        }
        uint32_t off = (uint32_t)((row << 7) | ((cc ^ (row & 7)) << 4));
        CP_ASYNC16(tb + off, gp);
    }
    CP_COMMIT();
}

__device__ void gemm_phase(uint32_t sb, const __half* Am, const __half* Bm,
                           float* part, int Kdim, int Ctot, int c0, int ks)
{
    const int tid = threadIdx.x;
    const int k0 = ks * 512;
    const int nst = 512 / KT;                  // 8 stages

    const int warp = tid >> 5, lane = tid & 31;
    const int wm = warp >> 2;
    const int wn = warp & 3;
    const int lrow = lane & 15;
    const int lhalf = lane >> 4;
    const int lsw = lrow & 7;

    float acc[2][2][4];
#pragma unroll
    for (int am = 0; am < 2; am++)
#pragma unroll
        for (int sel = 0; sel < 2; sel++)
#pragma unroll
            for (int v = 0; v < 4; v++) acc[am][sel][v] = 0.0f;

    issue_stage(sb, 0, tid, Am, Bm, Kdim, c0, k0);

    for (int s = 0; s < nst; s++) {
        if (s + 1 < nst) {
            issue_stage(sb, (s + 1) & 1, tid, Am, Bm, Kdim, c0, k0 + (s + 1) * KT);
            CP_WAIT1();
        } else {
            CP_COMMIT();
            CP_WAIT0();
        }
        __syncthreads();

        uint32_t bufb = sb + (s & 1) * BUF_BYTES;
#pragma unroll
        for (int kk = 0; kk < 4; kk++) {
            uint32_t ksel = (uint32_t)((((kk << 1) | lhalf) ^ lsw) << 4);
            uint32_t ah[2][4], bb[4];
#pragma unroll
            for (int am = 0; am < 2; am++) {
                uint32_t rb = (uint32_t)((wm * 32 + am * 16 + lrow) << 7) + ksel;
                ldsm4(ah[am], bufb + rb);
            }
            {
                uint32_t rb = (uint32_t)((wn * 16 + lrow) << 7) + ksel;
                ldsm4(bb, bufb + 16384u + rb);
            }
#pragma unroll
            for (int am = 0; am < 2; am++)
#pragma unroll
                for (int sel = 0; sel < 2; sel++)
                    mma_fp16(acc[am][sel], ah[am], bb[sel], bb[sel + 2]);
        }
        __syncthreads();
    }

    const int qrow = lane >> 2, qcol2 = (lane & 3) << 1;
    float* po = part + (size_t)ks * Ctot * 64;
#pragma unroll
    for (int am = 0; am < 2; am++)
#pragma unroll
        for (int sel = 0; sel < 2; sel++) {
            int c = c0 + wm * 32 + am * 16 + qrow;
            int col = wn * 16 + sel * 8 + qcol2;
            *reinterpret_cast<float2*>(&po[(size_t)c * 64 + col]) =
                make_float2(acc[am][sel][0], acc[am][sel][1]);
            *reinterpret_cast<float2*>(&po[(size_t)(c + 8) * 64 + col]) =
                make_float2(acc[am][sel][2], acc[am][sel][3]);
        }
}

// ---------------- persistent kernel ----------------
__global__ __launch_bounds__(NTHREADS, 1) void ista_persist(float* __restrict__ out) {
    extern __shared__ char smem[];
    uint32_t sb = smem_u32(smem);
    const int cta = blockIdx.x;
    const int t = threadIdx.x;
    unsigned nb = 0;

    float* xc = g_xA;
    float* xn = g_xB;

    for (int it = 0; it < NITER; it++) {
        // ---- fwd gemm: pf[ks] = Kf[c-tile] @ x ----
        gemm_phase(sb, g_Kf, g_x, g_pf, NI, MI, (cta & 15) * MT, cta >> 4);
        grid_bar(++nb, cta);

        // ---- err reduce + fp16 conv (CTA: 16 c x 64 b) ----
        {
            float (*tile)[65] = reinterpret_cast<float(*)[65]>(smem);
            const int c0 = cta * 16;
            {
                const int b = t & 63, cl0 = t >> 6;
#pragma unroll
                for (int i = 0; i < 2; i++) {
                    int cl = cl0 + i * 8;
                    int c = c0 + cl;
                    float s = 0.0f;
#pragma unroll
                    for (int p = 0; p < FWD_SPLIT; p++)
                        s += g_pf[(size_t)p * MI * 64 + c * 64 + b];
                    tile[cl][b] = s - g_yT[c * 64 + b];
                }
            }
            __syncthreads();
            {
                const int cl = t & 15, brow = t >> 4;
#pragma unroll
                for (int i = 0; i < 2; i++) {
                    int b = brow + i * 32;
                    g_e[b * MI + c0 + cl] = __float2half(tile[cl][b]);
                }
            }
        }
        grid_bar(++nb, cta);

        // ---- bwd gemm: pb[ks] = Kb[c-tile] @ e ----
        gemm_phase(sb, g_Kb, g_e, g_pb, MI, NI, (cta >> 2) * MT, cta & 3);
        grid_bar(++nb, cta);

        // ---- update + shrink + fp16 conv (CTA: 32 c x 64 b) ----
        {
            float (*tile)[65] = reinterpret_cast<float(*)[65]>(smem);
            const int c0 = cta * 32;
            {
                const int b = t & 63, cl0 = t >> 6;
#pragma unroll
                for (int i = 0; i < 4; i++) {
                    int cl = cl0 + i * 8;
                    int c = c0 + cl;
                    float g = 0.0f;
#pragma unroll
                    for (int p = 0; p < BWD_SPLIT; p++)
                        g += g_pb[(size_t)p * NI * 64 + c * 64 + b];
                    float xv = xc[c * 64 + b] - STEPF * g;
                    int kb = c & 7;
                    float thr = (kb == 0) ? 0.0f : ((kb == 7) ? 0.002f : 0.001f);
                    float a = fabsf(xv) - thr;
                    float r = (a > 0.0f) ? copysignf(a, xv) : 0.0f;
                    xn[c * 64 + b] = r;
                    tile[cl][b] = r;
                }
            }
            __syncthreads();
            {
                const int cl = t & 31, brow = t >> 5;
#pragma unroll
                for (int i = 0; i < 4; i++) {
                    int b = brow + i * 16;
                    g_x[b * NI + c0 + cl] = __float2half(tile[cl][b]);
                }
            }
        }
        grid_bar(++nb, cta);

        float* tmp = xc; xc = xn; xn = tmp;
    }

    // ---- write out[b][n][k] = x[c][b] ----
    {
        const int c0 = cta * 32;
#pragma unroll
        for (int i = 0; i < 4; i++) {
            int idx = t + i * NTHREADS;        // 2048 per CTA
            int b = idx >> 5, c = c0 + (idx & 31);
            out[(size_t)b * NI + c] = xc[c * 64 + b];
        }
    }
}

// ---------------- host ----------------
extern "C" void kernel_launch(void* const* d_in, const int* in_sizes, int n_in,
                              void* d_out, int out_size)
{
    const float* y = (const float*)d_in[0];
    const float* A = (const float*)d_in[1];
    if (n_in >= 2 && in_sizes[0] > in_sizes[1]) {
        const float* t = y; y = A; A = t;
    }

    cudaFuncSetAttribute(ista_persist, cudaFuncAttributeMaxDynamicSharedMemorySize, SMEM_TOTAL);

    build_kf<<<(int)(((size_t)MI * NI + 255) / 256), 256>>>(A);
    build_kb<<<(int)(((size_t)NI * MI + 255) / 256), 256>>>(A);
    build_yT<<<(MI * BDIM + 255) / 256, 256>>>(y);
    init_x<<<(BDIM * NI + 255) / 256, 256>>>();

    ista_persist<<<GRID, NTHREADS, SMEM_TOTAL>>>((float*)d_out);
}

// round 9
// speedup vs baseline: 2.2159x; 1.1723x over previous
#include <cuda_runtime.h>
#include <cuda_fp16.h>
#include <cstdint>

// CliffordISTA — Round 8: Cl(3,0) ≅ M2(C) (Pauli) representation.
// Geometric-product GEMMs become complex GEMMs (realified), HALF the real MACs
// of the dense Cayley operator. fp16 operands, fp32 accumulate.
// Persistent kernel + software grid barriers (R7 infra).
//
// Blade order (bitmask): [1, e1, e2, e12, e3, e13, e23, e123]
// M(v) = [[ (v0+v4) + i(v3+v7),  (v1-v5) + i(-v2+v6) ],
//         [ (v1+v5) + i(v2+v6),  (v0-v4) + i(-v3+v7) ]]
// x*A (x left)  -> M(x)·M(A);  reversion -> conjugate transpose.
//
// Realified layouts:
//   X [row=2b+p][k=4n+2q+ri]   (128 x 2048)  ri: 0=Re,1=Im of M(x[b,n])[p][q]
//   Wf[col=4m+2p'+ro][k=4n+2q+ri] (1024 x 2048), from M(A[m,n])[q][p']
//   Y/E [row][4m+2p'+ro]       (128 x 1024)  — fwd output IS bwd input layout
//   Wb[col=4n+2q'+ro][k=4m+2p+ri] (2048 x 1024), from conj(M(A[m,n])[q'][p])
//   G  [row][4n+2q+ro]         (128 x 2048)  — same layout as X

#define NDIM 512
#define MDIM 256
#define BDIM 64
#define NITER 50
#define STEPF 0.01f
#define KT 64
#define NTHREADS 512
#define GRID 128
#define FWD_SPLIT 8
#define BWD_SPLIT 4
#define KRF 2048   // fwd realified K  (4*NDIM)
#define CCF 1024   // fwd out cols     (4*MDIM)
#define KRB 1024   // bwd realified K
#define CCB 2048   // bwd out cols

#define BUF_BYTES 24576  // per stage: A-op 16K | B-op 8K
#define SMEM_TOTAL (2 * BUF_BYTES)

// ---------------- device globals ----------------
__device__ __half g_Wf[(size_t)CCF * KRF];   // [col][k]  4MB
__device__ __half g_Wb[(size_t)CCB * KRB];   // [col][k]  4MB
__device__ __half g_X[128 * KRF];            // realified x
__device__ __half g_E[128 * KRB];            // realified err
__device__ float g_xs[BDIM * NDIM * 8];      // blade state == output layout
__device__ float g_yr[128 * CCF];            // realified y
__device__ float g_pf[(size_t)FWD_SPLIT * 128 * CCF];
__device__ float g_pb[(size_t)BWD_SPLIT * 128 * CCB];
__device__ unsigned g_sub[8 * 32];
__device__ unsigned g_root;

// ---------------- helpers ----------------
__device__ __forceinline__ uint32_t smem_u32(const void* p) {
    uint32_t a;
    asm("{ .reg .u64 t; cvta.to.shared.u64 t, %1; cvt.u32.u64 %0, t; }" : "=r"(a) : "l"(p));
    return a;
}

#define CP_ASYNC16(smem, gptr) \
    asm volatile("cp.async.cg.shared.global [%0], [%1], 16;" :: "r"(smem), "l"(gptr))
#define CP_COMMIT() asm volatile("cp.async.commit_group;" ::: "memory")
#define CP_WAIT1()  asm volatile("cp.async.wait_group 1;" ::: "memory")
#define CP_WAIT0()  asm volatile("cp.async.wait_group 0;" ::: "memory")

__device__ __forceinline__ void ldsm4(uint32_t* r, uint32_t addr) {
    asm volatile("ldmatrix.sync.aligned.m8n8.x4.shared.b16 {%0,%1,%2,%3}, [%4];"
                 : "=r"(r[0]), "=r"(r[1]), "=r"(r[2]), "=r"(r[3]) : "r"(addr));
}

__device__ __forceinline__ void mma_fp16(float* c, const uint32_t* a, uint32_t b0, uint32_t b1) {
    asm volatile(
        "mma.sync.aligned.m16n8k16.row.col.f32.f16.f16.f32 "
        "{%0,%1,%2,%3}, {%4,%5,%6,%7}, {%8,%9}, {%0,%1,%2,%3};"
        : "+f"(c[0]), "+f"(c[1]), "+f"(c[2]), "+f"(c[3])
        : "r"(a[0]), "r"(a[1]), "r"(a[2]), "r"(a[3]), "r"(b0), "r"(b1));
}

// M(v)[q][p] for blade vector v[8]
__device__ __forceinline__ void pauli_entry(const float* v, int q, int p,
                                            float* re, float* im) {
    if (q == 0) {
        if (p == 0) { *re = v[0] + v[4]; *im = v[3] + v[7]; }
        else        { *re = v[1] - v[5]; *im = -v[2] + v[6]; }
    } else {
        if (p == 0) { *re = v[1] + v[5]; *im = v[2] + v[6]; }
        else        { *re = v[0] - v[4]; *im = -v[3] + v[7]; }
    }
}

// grid barrier (monotonic, zeroed by init each launch)
__device__ __forceinline__ void grid_bar(unsigned nb, int cta) {
    __syncthreads();
    if (threadIdx.x == 0) {
        __threadfence();
        unsigned prev = atomicAdd(&g_sub[(cta & 7) * 32], 1u);
        if (prev + 1u == 16u * nb)
            atomicAdd(&g_root, 1u);
        unsigned target = 8u * nb, v;
        do {
            asm volatile("ld.volatile.global.u32 %0, [%1];" : "=r"(v) : "l"(&g_root));
        } while ((int)(v - target) < 0);
        __threadfence();
    }
    __syncthreads();
}

// ---------------- build / init ----------------
__global__ void build_wf(const float* __restrict__ A) {
    size_t idx = (size_t)blockIdx.x * blockDim.x + threadIdx.x;
    if (idx >= (size_t)CCF * KRF) return;
    int col = (int)(idx >> 11), k = (int)(idx & (KRF - 1));
    int m = col >> 2, pp = (col >> 1) & 1, ro = col & 1;
    int n = k >> 2, q = (k >> 1) & 1, ri = k & 1;
    const float* a = A + ((size_t)m * NDIM + n) * 8;
    float re, im;
    pauli_entry(a, q, pp, &re, &im);
    float v = (ri == 0) ? (ro == 0 ? re : im) : (ro == 0 ? -im : re);
    g_Wf[idx] = __float2half(v);
}

__global__ void build_wb(const float* __restrict__ A) {
    size_t idx = (size_t)blockIdx.x * blockDim.x + threadIdx.x;
    if (idx >= (size_t)CCB * KRB) return;
    int col = (int)(idx >> 10), k = (int)(idx & (KRB - 1));
    int n = col >> 2, qp = (col >> 1) & 1, ro = col & 1;
    int m = k >> 2, p = (k >> 1) & 1, ri = k & 1;
    const float* a = A + ((size_t)m * NDIM + n) * 8;
    float re, im;
    pauli_entry(a, qp, p, &re, &im);       // M(A)[q'][p]; conj applied via signs
    float v = (ri == 0) ? (ro == 0 ? re : -im) : (ro == 0 ? im : re);
    g_Wb[idx] = __float2half(v);
}

__global__ void build_yr(const float* __restrict__ y) {
    int idx = blockIdx.x * blockDim.x + threadIdx.x;
    if (idx >= 128 * CCF) return;
    int row = idx >> 10, col = idx & (CCF - 1);
    int b = row >> 1, p = row & 1;
    int m = col >> 2, pp = (col >> 1) & 1, ro = col & 1;
    const float* yv = y + ((size_t)b * MDIM + m) * 8;
    float re, im;
    pauli_entry(yv, p, pp, &re, &im);
    g_yr[idx] = ro ? im : re;
}

__global__ void init_all() {
    int idx = blockIdx.x * blockDim.x + threadIdx.x;
    if (idx < BDIM * NDIM * 8) g_xs[idx] = 0.0f;
    if (idx < 128 * KRF) g_X[idx] = __float2half(0.0f);
    if (idx < 8 * 32) g_sub[idx] = 0u;
    if (idx == 0) g_root = 0u;
}

// ---------------- gemm phase ----------------
// A-op = Xm rows 0..127 [row][k]; B-op = Wm rows c0..c0+63 [col][k]; both stride Kdim.
__device__ __forceinline__ void issue_stage(
    uint32_t sb, int buf, int tid, const __half* Xm, const __half* Wm,
    int Kdim, int c0, int kk)
{
    uint32_t base = sb + buf * BUF_BYTES;
#pragma unroll
    for (int r = 0; r < 3; r++) {
        int q = tid + (r << 9);                // 1536 16B chunks per stage
        const __half* gp;
        uint32_t tb;
        int row, cc;
        if (q < 1024) {                        // A: 128 rows x 8 chunks
            row = q >> 3; cc = q & 7;
            gp = Xm + (size_t)row * Kdim + kk + cc * 8;
            tb = base;
        } else {                               // B: 64 rows x 8 chunks
            int q2 = q - 1024;
            row = q2 >> 3; cc = q2 & 7;
            gp = Wm + (size_t)(c0 + row) * Kdim + kk + cc * 8;
            tb = base + 16384;
        }
        uint32_t off = (uint32_t)((row << 7) | ((cc ^ (row & 7)) << 4));
        CP_ASYNC16(tb + off, gp);
    }
    CP_COMMIT();
}

__device__ void gemm_phase(uint32_t sb, const __half* Xm, const __half* Wm,
                           float* part, int Kdim, int Cc, int c0, int ks)
{
    const int tid = threadIdx.x;
    const int k0 = ks * 256;
    const int nst = 256 / KT;                  // 4 stages

    const int warp = tid >> 5, lane = tid & 31;
    const int wm = warp >> 2;
    const int wn = warp & 3;
    const int lrow = lane & 15;
    const int lhalf = lane >> 4;
    const int lsw = lrow & 7;

    float acc[2][2][4];
#pragma unroll
    for (int am = 0; am < 2; am++)
#pragma unroll
        for (int sel = 0; sel < 2; sel++)
#pragma unroll
            for (int v = 0; v < 4; v++) acc[am][sel][v] = 0.0f;

    issue_stage(sb, 0, tid, Xm, Wm, Kdim, c0, k0);

    for (int s = 0; s < nst; s++) {
        if (s + 1 < nst) {
            issue_stage(sb, (s + 1) & 1, tid, Xm, Wm, Kdim, c0, k0 + (s + 1) * KT);
            CP_WAIT1();
        } else {
            CP_COMMIT();
            CP_WAIT0();
        }
        __syncthreads();

        uint32_t bufb = sb + (s & 1) * BUF_BYTES;
#pragma unroll
        for (int kk = 0; kk < 4; kk++) {
            uint32_t ksel = (uint32_t)((((kk << 1) | lhalf) ^ lsw) << 4);
            uint32_t ah[2][4], bb[4];
#pragma unroll
            for (int am = 0; am < 2; am++) {
                uint32_t rb = (uint32_t)((wm * 32 + am * 16 + lrow) << 7) + ksel;
                ldsm4(ah[am], bufb + rb);
            }
            {
                uint32_t rb = (uint32_t)((wn * 16 + lrow) << 7) + ksel;
                ldsm4(bb, bufb + 16384u + rb);
            }
#pragma unroll
            for (int am = 0; am < 2; am++)
#pragma unroll
                for (int sel = 0; sel < 2; sel++)
                    mma_fp16(acc[am][sel], ah[am], bb[sel], bb[sel + 2]);
        }
        __syncthreads();
    }

    const int qrow = lane >> 2, qcol2 = (lane & 3) << 1;
    float* po = part + (size_t)ks * 128 * Cc;
#pragma unroll
    for (int am = 0; am < 2; am++)
#pragma unroll
        for (int sel = 0; sel < 2; sel++) {
            int row = wm * 32 + am * 16 + qrow;
            int col = c0 + wn * 16 + sel * 8 + qcol2;
            *reinterpret_cast<float2*>(&po[(size_t)row * Cc + col]) =
                make_float2(acc[am][sel][0], acc[am][sel][1]);
            *reinterpret_cast<float2*>(&po[(size_t)(row + 8) * Cc + col]) =
                make_float2(acc[am][sel][2], acc[am][sel][3]);
        }
}

// ---------------- persistent kernel ----------------
__global__ __launch_bounds__(NTHREADS, 1) void ista_persist(float* __restrict__ out) {
    extern __shared__ char smem[];
    uint32_t sb = smem_u32(smem);
    const int cta = blockIdx.x;
    const int t = threadIdx.x;
    unsigned nb = 0;

    for (int it = 0; it < NITER; it++) {
        // ---- fwd: pf[ks] = X(128x2048) @ Wf-tile ----
        gemm_phase(sb, g_X, g_Wf, g_pf, KRF, CCF, (cta & 15) * 64, cta >> 4);
        grid_bar(++nb, cta);

        // ---- err: E = sum(pf) - yr, fp16 (128x1024, coalesced) ----
#pragma unroll
        for (int i = 0; i < 2; i++) {
            int idx = cta * NTHREADS + t + i * (GRID * NTHREADS);
            float s = 0.0f;
#pragma unroll
            for (int p = 0; p < FWD_SPLIT; p++)
                s += g_pf[(size_t)p * 128 * CCF + idx];
            g_E[idx] = __float2half(s - g_yr[idx]);
        }
        grid_bar(++nb, cta);

        // ---- bwd: pb[ks] = E(128x1024) @ Wb-tile ----
        gemm_phase(sb, g_E, g_Wb, g_pb, KRB, CCB, (cta >> 2) * 64, cta & 3);
        grid_bar(++nb, cta);

        // ---- upd: matrix->blade butterfly, shrink, blade->matrix ----
        {
            int idx = cta * NTHREADS + t;
            if (idx < BDIM * NDIM) {
                int b = idx >> 9, n = idx & (NDIM - 1);
                size_t base0 = (size_t)(2 * b) * CCB + 4 * n;
                size_t base1 = base0 + CCB;
                float4 G0 = make_float4(0.f, 0.f, 0.f, 0.f);
                float4 G1 = make_float4(0.f, 0.f, 0.f, 0.f);
#pragma unroll
                for (int p = 0; p < BWD_SPLIT; p++) {
                    float4 a = *reinterpret_cast<const float4*>(
                        &g_pb[(size_t)p * 128 * CCB + base0]);
                    float4 c = *reinterpret_cast<const float4*>(
                        &g_pb[(size_t)p * 128 * CCB + base1]);
                    G0.x += a.x; G0.y += a.y; G0.z += a.z; G0.w += a.w;
                    G1.x += c.x; G1.y += c.y; G1.z += c.z; G1.w += c.w;
                }
                // M(g): [p][q] Re=col 4n+2q, Im=+1
                float g[8];
                g[0] = 0.5f * (G0.x + G1.z);   // scalar
                g[4] = 0.5f * (G0.x - G1.z);   // e3
                g[3] = 0.5f * (G0.y - G1.w);   // e12
                g[7] = 0.5f * (G0.y + G1.w);   // e123
                g[1] = 0.5f * (G0.z + G1.x);   // e1
                g[5] = 0.5f * (G1.x - G0.z);   // e13
                g[2] = 0.5f * (G1.y - G0.w);   // e2
                g[6] = 0.5f * (G0.w + G1.y);   // e23

                float* xs = g_xs + (size_t)idx * 8;
                float x[8];
#pragma unroll
                for (int i = 0; i < 8; i++) {
                    float xv = xs[i] - STEPF * g[i];
                    float thr = (i == 0) ? 0.0f : ((i == 7) ? 0.002f : 0.001f);
                    float a = fabsf(xv) - thr;
                    x[i] = (a > 0.0f) ? copysignf(a, xv) : 0.0f;
                    xs[i] = x[i];
                }
                // blade -> matrix, fp16, rows 2b / 2b+1, cols 4n..4n+3
                __half2* X0 = reinterpret_cast<__half2*>(
                    &g_X[(size_t)(2 * b) * KRF + 4 * n]);
                __half2* X1 = reinterpret_cast<__half2*>(
                    &g_X[(size_t)(2 * b + 1) * KRF + 4 * n]);
                X0[0] = __floats2half2_rn(x[0] + x[4], x[3] + x[7]);
                X0[1] = __floats2half2_rn(x[1] - x[5], -x[2] + x[6]);
                X1[0] = __floats2half2_rn(x[1] + x[5], x[2] + x[6]);
                X1[1] = __floats2half2_rn(x[0] - x[4], -x[3] + x[7]);
            }
        }
        grid_bar(++nb, cta);
    }

    // ---- out = blade state (already in output layout) ----
    {
        int idx = cta * NTHREADS + t;          // 65536 threads x float4 = 1MB
        reinterpret_cast<float4*>(out)[idx] =
            reinterpret_cast<const float4*>(g_xs)[idx];
    }
}

// ---------------- host ----------------
extern "C" void kernel_launch(void* const* d_in, const int* in_sizes, int n_in,
                              void* d_out, int out_size)
{
    const float* y = (const float*)d_in[0];
    const float* A = (const float*)d_in[1];
    if (n_in >= 2 && in_sizes[0] > in_sizes[1]) {
        const float* t = y; y = A; A = t;
    }

    cudaFuncSetAttribute(ista_persist, cudaFuncAttributeMaxDynamicSharedMemorySize, SMEM_TOTAL);

    build_wf<<<(int)(((size_t)CCF * KRF + 255) / 256), 256>>>(A);
    build_wb<<<(int)(((size_t)CCB * KRB + 255) / 256), 256>>>(A);
    build_yr<<<(128 * CCF + 255) / 256, 256>>>(y);
    init_all<<<(128 * KRF + 255) / 256, 256>>>();

    ista_persist<<<GRID, NTHREADS, SMEM_TOTAL>>>((float*)d_out);
}